// round 6
// baseline (speedup 1.0000x reference)
#include <cuda_runtime.h>
#include <cuda_bf16.h>
#include <cstdint>
#include <math.h>

typedef __nv_bfloat16 bf16;

#define BDIM 48
#define HDIM 56
#define WDIM 56
#define CDIM 256
#define TDIM 3
#define NTOK 50176        /* (B/T)*H*W */
#define MROWS 150528      /* NTOK*T = B*H*W */
#define HID 1024
#define EPSLN 1e-6f

// ---------------- scratch (static device allocations) ----------------
__device__ bf16  g_xn  [(size_t)MROWS*CDIM];
__device__ bf16  g_kvq [(size_t)MROWS*3*CDIM];
__device__ bf16  g_attn[(size_t)MROWS*CDIM];
__device__ bf16  g_po  [(size_t)MROWS*CDIM];   /* proj_out + bias, bf16 */
__device__ bf16  g_xtn [(size_t)MROWS*CDIM];
__device__ bf16  g_h   [(size_t)MROWS*HID];
__device__ bf16  g_wkvq[3*CDIM*CDIM];
__device__ bf16  g_wproj[CDIM*CDIM];
__device__ bf16  g_wfc1[HID*CDIM];
__device__ bf16  g_wfc2[CDIM*HID];

// ---------------- small helpers ----------------
__device__ __forceinline__ uint32_t pack_bf2(float a, float b) {
    __nv_bfloat162 h = __float22bfloat162_rn(make_float2(a, b));
    return *reinterpret_cast<uint32_t*>(&h);
}
__device__ __forceinline__ uint32_t s2u(const void* p) {
    uint32_t a;
    asm("{ .reg .u64 t; cvta.to.shared.u64 t, %1; cvt.u32.u64 %0, t; }" : "=r"(a) : "l"(p));
    return a;
}
#define CP_ASYNC16(saddr, gptr) \
    asm volatile("cp.async.cg.shared.global [%0], [%1], 16;" :: "r"(saddr), "l"(gptr) : "memory")
#define CP_COMMIT() asm volatile("cp.async.commit_group;" ::: "memory")

#define LDSM_X4(r0, r1, r2, r3, a) \
    asm volatile("ldmatrix.sync.aligned.m8n8.x4.shared.b16 {%0,%1,%2,%3}, [%4];" \
        : "=r"(r0), "=r"(r1), "=r"(r2), "=r"(r3) : "r"(a))

#define HMMA(acc, a0, a1, a2, a3, b0, b1) \
    asm volatile( \
        "mma.sync.aligned.m16n8k16.row.col.f32.bf16.bf16.f32 " \
        "{%0,%1,%2,%3}, {%4,%5,%6,%7}, {%8,%9}, {%0,%1,%2,%3};\n" \
        : "+f"((acc)[0]), "+f"((acc)[1]), "+f"((acc)[2]), "+f"((acc)[3]) \
        : "r"(a0), "r"(a1), "r"(a2), "r"(a3), "r"(b0), "r"(b1))

// ---------------- weight fp32 -> bf16 ----------------
__global__ void convw_kernel(const float* __restrict__ wkvq, const float* __restrict__ wproj,
                             const float* __restrict__ wfc1, const float* __restrict__ wfc2) {
    int i = blockIdx.x * 256 + threadIdx.x;
    if (i < 3*CDIM*CDIM) g_wkvq[i]  = __float2bfloat16(wkvq[i]);
    if (i < CDIM*CDIM)   g_wproj[i] = __float2bfloat16(wproj[i]);
    if (i < HID*CDIM) {
        g_wfc1[i] = __float2bfloat16(wfc1[i]);
        g_wfc2[i] = __float2bfloat16(wfc2[i]);
    }
}

// ---------------- LN1: warp per row ----------------
__device__ __forceinline__ void warpLN8(float* v, float& mu, float& rstd) {
    float s = 0.f, s2 = 0.f;
    #pragma unroll
    for (int j = 0; j < 8; j++) { s += v[j]; s2 += v[j] * v[j]; }
    #pragma unroll
    for (int o = 16; o; o >>= 1) {
        s  += __shfl_xor_sync(0xffffffffu, s,  o);
        s2 += __shfl_xor_sync(0xffffffffu, s2, o);
    }
    mu = s * (1.f / CDIM);
    rstd = rsqrtf(s2 * (1.f / CDIM) - mu * mu + EPSLN);
}

__global__ void ln1_kernel(const float* __restrict__ x, const float* __restrict__ w,
                           const float* __restrict__ b) {
    int r = blockIdx.x * 8 + (threadIdx.x >> 5);
    int lane = threadIdx.x & 31;
    const float4* px = (const float4*)(x + (size_t)r * CDIM);
    float4 a0 = px[lane * 2], a1 = px[lane * 2 + 1];
    float v[8] = {a0.x, a0.y, a0.z, a0.w, a1.x, a1.y, a1.z, a1.w};
    float mu, rstd;
    warpLN8(v, mu, rstd);
    float4 w0 = ((const float4*)w)[lane*2], w1 = ((const float4*)w)[lane*2+1];
    float4 b0 = ((const float4*)b)[lane*2], b1 = ((const float4*)b)[lane*2+1];
    float wv[8] = {w0.x,w0.y,w0.z,w0.w,w1.x,w1.y,w1.z,w1.w};
    float bv[8] = {b0.x,b0.y,b0.z,b0.w,b1.x,b1.y,b1.z,b1.w};
    uint32_t o[4];
    #pragma unroll
    for (int j = 0; j < 4; j++) {
        float y0 = (v[2*j]   - mu) * rstd * wv[2*j]   + bv[2*j];
        float y1 = (v[2*j+1] - mu) * rstd * wv[2*j+1] + bv[2*j+1];
        o[j] = pack_bf2(y0, y1);
    }
    int ww = r % WDIM; int r2 = r / WDIM;
    int hh = r2 % HDIM; int bb = r2 / HDIM;
    int bh = bb / TDIM, t = bb - bh * TDIM;
    int m = ((bh * HDIM + hh) * WDIM + ww) * TDIM + t;
    ((uint4*)(g_xn + (size_t)m * CDIM))[lane] = make_uint4(o[0], o[1], o[2], o[3]);
}

// ---------------- attention: one THREAD per (n, head); T=3, DH=32 ----------------
__device__ __forceinline__ void u4tof(uint4 u, float2* f) {
    f[0] = __bfloat1622float2(*(__nv_bfloat162*)&u.x);
    f[1] = __bfloat1622float2(*(__nv_bfloat162*)&u.y);
    f[2] = __bfloat1622float2(*(__nv_bfloat162*)&u.z);
    f[3] = __bfloat1622float2(*(__nv_bfloat162*)&u.w);
}

__global__ void attn_kernel() {
    int gid = blockIdx.x * 256 + threadIdx.x;   // NTOK*8 threads
    int n = gid >> 3, h = gid & 7;
    const uint4* base = (const uint4*)(g_kvq + (size_t)n * 2304 + h * 32);
    float dot[3][3];
    #pragma unroll
    for (int a = 0; a < 3; a++)
        #pragma unroll
        for (int s = 0; s < 3; s++) dot[a][s] = 0.f;
    #pragma unroll
    for (int d8 = 0; d8 < 4; d8++) {
        float2 qv[3][4], kv[3][4];
        #pragma unroll
        for (int t = 0; t < 3; t++) {
            u4tof(base[(t*768 + 512) / 8 + d8], qv[t]);
            u4tof(base[(t*768 +   0) / 8 + d8], kv[t]);
        }
        #pragma unroll
        for (int a = 0; a < 3; a++)
            #pragma unroll
            for (int s = 0; s < 3; s++)
                #pragma unroll
                for (int j = 0; j < 4; j++)
                    dot[a][s] += qv[a][j].x * kv[s][j].x + qv[a][j].y * kv[s][j].y;
    }
    float wgt[3][3];
    #pragma unroll
    for (int a = 0; a < 3; a++) {
        float l0 = dot[a][0] * 0.17677669529663687f;
        float l1 = dot[a][1] * 0.17677669529663687f;
        float l2 = dot[a][2] * 0.17677669529663687f;
        float mx = fmaxf(l0, fmaxf(l1, l2));
        float e0 = __expf(l0 - mx), e1 = __expf(l1 - mx), e2 = __expf(l2 - mx);
        float inv = 1.f / (e0 + e1 + e2);
        wgt[a][0] = e0 * inv; wgt[a][1] = e1 * inv; wgt[a][2] = e2 * inv;
    }
    #pragma unroll
    for (int d8 = 0; d8 < 4; d8++) {
        float2 vv[3][4];
        #pragma unroll
        for (int t = 0; t < 3; t++) u4tof(base[(t*768 + 256) / 8 + d8], vv[t]);
        #pragma unroll
        for (int a = 0; a < 3; a++) {
            uint32_t o[4];
            #pragma unroll
            for (int j = 0; j < 4; j++) {
                float ox = wgt[a][0]*vv[0][j].x + wgt[a][1]*vv[1][j].x + wgt[a][2]*vv[2][j].x;
                float oy = wgt[a][0]*vv[0][j].y + wgt[a][1]*vv[1][j].y + wgt[a][2]*vv[2][j].y;
                o[j] = pack_bf2(ox, oy);
            }
            *(uint4*)(g_attn + (size_t)(n*3 + a) * CDIM + h*32 + d8*8) =
                make_uint4(o[0], o[1], o[2], o[3]);
        }
    }
}

// ====== main GEMM: 256x128 tile, 512 threads, warp 64x32, 4-stage ring ======
#define BM 256
#define BN 128
#define BKK 32
#define LDSS 40                 /* 80B rows: conflict-free ldmatrix */
#define S4 4
#define A_BYTES (BM * LDSS * 2)                     /* 20480 */
#define B_BYTES (BN * LDSS * 2)                     /* 10240 */
#define GEMM_SMEM (S4 * (A_BYTES + B_BYTES))        /* 122880 */

// EPI: 0 = kvq (bias -> bf16 g_kvq)   2 = fc1 (bias + gelu -> bf16 g_h)
//      3 = fc2 (bias + po + x residual -> fp32 out)
template<int EPI, int NDIM, int KDIM>
__global__ void __launch_bounds__(512, 1) gemm_kernel(const float* __restrict__ bias,
                                                      const float* __restrict__ xres,
                                                      float* __restrict__ gout) {
    constexpr int NKT = KDIM / BKK;
    const bf16 *A, *W;
    if constexpr (EPI == 0)      { A = g_xn;   W = g_wkvq;  }
    else if constexpr (EPI == 2) { A = g_xtn;  W = g_wfc1;  }
    else                         { A = g_h;    W = g_wfc2;  }

    extern __shared__ char dsm[];
    const uint32_t sA0 = s2u(dsm);
    const uint32_t sB0 = sA0 + S4 * A_BYTES;

    const int bn = blockIdx.x, bm = blockIdx.y;
    const int tid = threadIdx.x;
    const int warp = tid >> 5, lane = tid & 31;
    const int wm = warp & 3, wn = warp >> 2;      // 4x4 warp grid, warp tile 64x32
    const int gro = lane >> 2, thr = lane & 3;
    const size_t aBase = (size_t)bm * BM * KDIM;
    const size_t bBase = (size_t)bn * BN * KDIM;

    const int aRow = wm * 64 + (lane & 7) + ((lane >> 3) & 1) * 8;   // + mi*16
    const int aCol = (lane >> 4) * 8;
    const int bRow = wn * 32 + (lane & 7) + (lane >> 4) * 8;         // + pr*16
    const int bCol = ((lane >> 3) & 1) * 8;

    auto loadTile = [&](int st, int kt) {
        int k0 = kt * BKK;
        // A: 256 rows x 4 chunks = 1024, 2/thread
        #pragma unroll
        for (int i = 0; i < 2; i++) {
            int idx = tid + i * 512;
            int row = idx >> 2, ch = idx & 3;
            CP_ASYNC16(sA0 + st * A_BYTES + (uint32_t)((row * LDSS + ch * 8) * 2),
                       A + aBase + (size_t)row * KDIM + k0 + ch * 8);
        }
        // B: 128 rows x 4 chunks = 512, 1/thread
        {
            int row = tid >> 2, ch = tid & 3;
            CP_ASYNC16(sB0 + st * B_BYTES + (uint32_t)((row * LDSS + ch * 8) * 2),
                       W + bBase + (size_t)row * KDIM + k0 + ch * 8);
        }
        CP_COMMIT();
    };

    float acc[4][4][4];
    #pragma unroll
    for (int i = 0; i < 4; i++)
        #pragma unroll
        for (int j = 0; j < 4; j++)
            #pragma unroll
            for (int l = 0; l < 4; l++) acc[i][j][l] = 0.f;

    #pragma unroll
    for (int s = 0; s < S4 - 1; s++) loadTile(s, s);

    for (int kt = 0; kt < NKT; kt++) {
        if (kt < NKT - 2)       asm volatile("cp.async.wait_group 2;" ::: "memory");
        else if (kt == NKT - 2) asm volatile("cp.async.wait_group 1;" ::: "memory");
        else                    asm volatile("cp.async.wait_group 0;" ::: "memory");
        __syncthreads();
        if (kt + S4 - 1 < NKT) loadTile((kt + S4 - 1) & (S4 - 1), kt + S4 - 1);
        const int st = kt & (S4 - 1);
        #pragma unroll
        for (int ks = 0; ks < 2; ks++) {
            uint32_t af[4][4];
            #pragma unroll
            for (int mi = 0; mi < 4; mi++) {
                uint32_t addr = sA0 + st * A_BYTES +
                    (uint32_t)(((aRow + mi * 16) * LDSS + ks * 16 + aCol) * 2);
                LDSM_X4(af[mi][0], af[mi][1], af[mi][2], af[mi][3], addr);
            }
            uint32_t bfr[4][2];
            #pragma unroll
            for (int pr = 0; pr < 2; pr++) {
                uint32_t addr = sB0 + st * B_BYTES +
                    (uint32_t)(((bRow + pr * 16) * LDSS + ks * 16 + bCol) * 2);
                LDSM_X4(bfr[pr*2][0], bfr[pr*2][1], bfr[pr*2+1][0], bfr[pr*2+1][1], addr);
            }
            #pragma unroll
            for (int ni = 0; ni < 4; ni++)
                #pragma unroll
                for (int mi = 0; mi < 4; mi++)
                    HMMA(acc[mi][ni], af[mi][0], af[mi][1], af[mi][2], af[mi][3],
                         bfr[ni][0], bfr[ni][1]);
        }
    }

    // ---- epilogue ----
    const int cb = bn * BN + wn * 32 + thr * 2;
    #pragma unroll
    for (int mi = 0; mi < 4; mi++) {
        #pragma unroll
        for (int rr = 0; rr < 2; rr++) {
            int m = bm * BM + wm * 64 + mi * 16 + rr * 8 + gro;
            size_t xidx = 0;
            if constexpr (EPI == 3) {
                int t = m % 3;
                int n = m / 3;
                int ww = n % WDIM;
                int r2 = n / WDIM;
                int hh = r2 % HDIM;
                int bhat = r2 / HDIM;
                int b = bhat * TDIM + t;
                xidx = ((size_t)((b * HDIM + hh) * WDIM + ww)) * CDIM;
            }
            #pragma unroll
            for (int ni = 0; ni < 4; ni++) {
                int c = cb + ni * 8;
                float v0 = acc[mi][ni][rr * 2 + 0] + bias[c];
                float v1 = acc[mi][ni][rr * 2 + 1] + bias[c + 1];
                if constexpr (EPI == 0) {
                    *(uint32_t*)&g_kvq[(size_t)m * NDIM + c] = pack_bf2(v0, v1);
                } else if constexpr (EPI == 2) {
                    v0 = 0.5f * v0 * (1.f + erff(v0 * 0.7071067811865475f));
                    v1 = 0.5f * v1 * (1.f + erff(v1 * 0.7071067811865475f));
                    *(uint32_t*)&g_h[(size_t)m * NDIM + c] = pack_bf2(v0, v1);
                } else {
                    float2 pp = __bfloat1622float2(*(const __nv_bfloat162*)&g_po[(size_t)m * CDIM + c]);
                    float2 xx = *(const float2*)&xres[xidx + c];
                    *(float2*)&gout[xidx + c] = make_float2(v0 + pp.x + xx.x, v1 + pp.y + xx.y);
                }
            }
        }
    }
}

// ====== fused proj + residual + LN2: 64-row x full-256-col tile, 3-stage ring ======
#define PBM 64
#define PS 3
#define PA_BYTES (PBM * LDSS * 2)     /* 5120 */
#define PB_BYTES (CDIM * LDSS * 2)    /* 20480 */
#define PSTAGE (PA_BYTES + PB_BYTES)  /* 25600 */
#define PROJ_SMEM (PS * PSTAGE)       /* 76800 */

__global__ void __launch_bounds__(256, 2) projln_kernel(const float* __restrict__ bias,
                                                        const float* __restrict__ x,
                                                        const float* __restrict__ w2,
                                                        const float* __restrict__ b2) {
    constexpr int NKT = CDIM / BKK;   // 8
    extern __shared__ char dsm[];
    __shared__ float2 red[PBM][2];

    const uint32_t p0 = s2u(dsm);
    const int bm = blockIdx.x;
    const int tid = threadIdx.x;
    const int warp = tid >> 5, lane = tid & 31;
    const int wm = warp & 3, wn = warp >> 2;      // 4 (m) x 2 (n); warp tile 16x128
    const int gro = lane >> 2, thr = lane & 3;
    const size_t aBase = (size_t)bm * PBM * CDIM;

    const int aRow = wm * 16 + (lane & 7) + ((lane >> 3) & 1) * 8;
    const int aCol = (lane >> 4) * 8;
    const int bRow = wn * 128 + (lane & 7) + (lane >> 4) * 8;
    const int bCol = ((lane >> 3) & 1) * 8;

    auto loadTile = [&](int st, int kt) {
        int k0 = kt * BKK;
        uint32_t base = p0 + st * PSTAGE;
        {
            int row = tid >> 2, ch = tid & 3;
            CP_ASYNC16(base + (uint32_t)((row * LDSS + ch * 8) * 2),
                       g_attn + aBase + (size_t)row * CDIM + k0 + ch * 8);
        }
        {
            uint32_t bB = base + PA_BYTES;
            #pragma unroll
            for (int i = 0; i < 4; i++) {
                int idx = tid + i * 256;
                int row = idx >> 2, ch = idx & 3;
                CP_ASYNC16(bB + (uint32_t)((row * LDSS + ch * 8) * 2),
                           g_wproj + (size_t)row * CDIM + k0 + ch * 8);
            }
        }
        CP_COMMIT();
    };

    float acc[16][4];
    #pragma unroll
    for (int j = 0; j < 16; j++)
        #pragma unroll
        for (int l = 0; l < 4; l++) acc[j][l] = 0.f;

    loadTile(0, 0);
    loadTile(1, 1);
    for (int kt = 0; kt < NKT; kt++) {
        if (kt < NKT - 1) asm volatile("cp.async.wait_group 1;" ::: "memory");
        else              asm volatile("cp.async.wait_group 0;" ::: "memory");
        __syncthreads();
        if (kt + 2 < NKT) loadTile((kt + 2) % PS, kt + 2);
        const int st = kt % PS;
        uint32_t base = p0 + st * PSTAGE;
        #pragma unroll
        for (int ks = 0; ks < 2; ks++) {
            uint32_t af[4];
            LDSM_X4(af[0], af[1], af[2], af[3],
                    base + (uint32_t)((aRow * LDSS + ks * 16 + aCol) * 2));
            uint32_t bfr[16][2];
            #pragma unroll
            for (int pr = 0; pr < 8; pr++) {
                uint32_t addr = base + PA_BYTES +
                    (uint32_t)(((bRow + pr * 16) * LDSS + ks * 16 + bCol) * 2);
                LDSM_X4(bfr[pr*2][0], bfr[pr*2][1], bfr[pr*2+1][0], bfr[pr*2+1][1], addr);
            }
            #pragma unroll
            for (int ni = 0; ni < 16; ni++)
                HMMA(acc[ni], af[0], af[1], af[2], af[3], bfr[ni][0], bfr[ni][1]);
        }
    }

    // ---- epilogue: bias, write po(bf16), +x -> LN over full row -> xtn ----
    size_t xidx[2];
    #pragma unroll
    for (int rr = 0; rr < 2; rr++) {
        int ml = wm * 16 + rr * 8 + gro;
        int m = bm * PBM + ml;
        int t = m % 3;
        int n = m / 3;
        int ww = n % WDIM;
        int r2 = n / WDIM;
        int hh = r2 % HDIM;
        int bhat = r2 / HDIM;
        xidx[rr] = ((size_t)(((bhat * TDIM + t) * HDIM + hh) * WDIM + ww)) * CDIM;

        float s = 0.f, s2 = 0.f;
        #pragma unroll
        for (int ni = 0; ni < 16; ni++) {
            int c = wn * 128 + ni * 8 + thr * 2;
            float2 bb = *(const float2*)&bias[c];
            float v0 = acc[ni][rr*2+0] + bb.x;
            float v1 = acc[ni][rr*2+1] + bb.y;
            *(uint32_t*)&g_po[(size_t)m * CDIM + c] = pack_bf2(v0, v1);
            float2 xx = *(const float2*)&x[xidx[rr] + c];
            v0 += xx.x; v1 += xx.y;
            acc[ni][rr*2+0] = v0; acc[ni][rr*2+1] = v1;
            s += v0 + v1; s2 += v0*v0 + v1*v1;
        }
        #pragma unroll
        for (int o = 1; o < 4; o <<= 1) {
            s  += __shfl_xor_sync(0xffffffffu, s,  o);
            s2 += __shfl_xor_sync(0xffffffffu, s2, o);
        }
        if (thr == 0) red[ml][wn] = make_float2(s, s2);
    }
    __syncthreads();
    #pragma unroll
    for (int rr = 0; rr < 2; rr++) {
        int ml = wm * 16 + rr * 8 + gro;
        int m = bm * PBM + ml;
        float2 rA = red[ml][0], rB = red[ml][1];
        float mu = (rA.x + rB.x) * (1.f / CDIM);
        float var = (rA.y + rB.y) * (1.f / CDIM) - mu * mu;
        float rstd = rsqrtf(var + EPSLN);
        #pragma unroll
        for (int ni = 0; ni < 16; ni++) {
            int c = wn * 128 + ni * 8 + thr * 2;
            float2 ww2 = *(const float2*)&w2[c];
            float2 bb2 = *(const float2*)&b2[c];
            float y0 = (acc[ni][rr*2+0] - mu) * rstd * ww2.x + bb2.x;
            float y1 = (acc[ni][rr*2+1] - mu) * rstd * ww2.y + bb2.y;
            *(uint32_t*)&g_xtn[(size_t)m * CDIM + c] = pack_bf2(y0, y1);
        }
    }
}

// ---------------- launch ----------------
extern "C" void kernel_launch(void* const* d_in, const int* in_sizes, int n_in,
                              void* d_out, int out_size) {
    const float* x      = (const float*)d_in[0];
    const float* n1w    = (const float*)d_in[1];
    const float* n1b    = (const float*)d_in[2];
    const float* kvq_w  = (const float*)d_in[3];
    const float* kvq_b  = (const float*)d_in[4];
    const float* proj_w = (const float*)d_in[5];
    const float* proj_b = (const float*)d_in[6];
    const float* n2w    = (const float*)d_in[7];
    const float* n2b    = (const float*)d_in[8];
    const float* fc1_w  = (const float*)d_in[9];
    const float* fc1_b  = (const float*)d_in[10];
    const float* fc2_w  = (const float*)d_in[11];
    const float* fc2_b  = (const float*)d_in[12];
    float* out = (float*)d_out;

    static bool attrs_set = false;
    if (!attrs_set) {
        cudaFuncSetAttribute(gemm_kernel<0, 768, 256>,  cudaFuncAttributeMaxDynamicSharedMemorySize, GEMM_SMEM);
        cudaFuncSetAttribute(gemm_kernel<2, 1024, 256>, cudaFuncAttributeMaxDynamicSharedMemorySize, GEMM_SMEM);
        cudaFuncSetAttribute(gemm_kernel<3, 256, 1024>, cudaFuncAttributeMaxDynamicSharedMemorySize, GEMM_SMEM);
        cudaFuncSetAttribute(projln_kernel,             cudaFuncAttributeMaxDynamicSharedMemorySize, PROJ_SMEM);
        attrs_set = true;
    }

    convw_kernel<<<1024, 256>>>(kvq_w, proj_w, fc1_w, fc2_w);
    ln1_kernel<<<MROWS / 8, 256>>>(x, n1w, n1b);
    gemm_kernel<0, 768, 256><<<dim3(6, MROWS / BM), 512, GEMM_SMEM>>>(kvq_b, nullptr, nullptr);
    attn_kernel<<<(NTOK * 8) / 256, 256>>>();
    projln_kernel<<<MROWS / PBM, 256, PROJ_SMEM>>>(proj_b, x, n2w, n2b);
    gemm_kernel<2, 1024, 256><<<dim3(8, MROWS / BM), 512, GEMM_SMEM>>>(fc1_b, nullptr, nullptr);
    gemm_kernel<3, 256, 1024><<<dim3(2, MROWS / BM), 512, GEMM_SMEM>>>(fc2_b, x, out);
}

// round 7
// speedup vs baseline: 1.1067x; 1.1067x over previous
#include <cuda_runtime.h>
#include <cuda_bf16.h>
#include <cstdint>
#include <math.h>

typedef __nv_bfloat16 bf16;

#define BDIM 48
#define HDIM 56
#define WDIM 56
#define CDIM 256
#define TDIM 3
#define NTOK 50176        /* (B/T)*H*W */
#define MROWS 150528      /* NTOK*T = B*H*W */
#define HID 1024
#define EPSLN 1e-6f

// ---------------- scratch (static device allocations) ----------------
__device__ bf16  g_xn  [(size_t)MROWS*CDIM];
__device__ bf16  g_kvq [(size_t)MROWS*3*CDIM];
__device__ bf16  g_attn[(size_t)MROWS*CDIM];
__device__ bf16  g_po  [(size_t)MROWS*CDIM];   /* proj_out + bias, bf16 */
__device__ bf16  g_xtn [(size_t)MROWS*CDIM];
__device__ bf16  g_h   [(size_t)MROWS*HID];
__device__ bf16  g_wkvq[3*CDIM*CDIM];
__device__ bf16  g_wproj[CDIM*CDIM];
__device__ bf16  g_wfc1[HID*CDIM];
__device__ bf16  g_wfc2[CDIM*HID];

// ---------------- small helpers ----------------
__device__ __forceinline__ uint32_t pack_bf2(float a, float b) {
    __nv_bfloat162 h = __float22bfloat162_rn(make_float2(a, b));
    return *reinterpret_cast<uint32_t*>(&h);
}
__device__ __forceinline__ uint32_t s2u(const void* p) {
    uint32_t a;
    asm("{ .reg .u64 t; cvta.to.shared.u64 t, %1; cvt.u32.u64 %0, t; }" : "=r"(a) : "l"(p));
    return a;
}
#define CP_ASYNC16(saddr, gptr) \
    asm volatile("cp.async.cg.shared.global [%0], [%1], 16;" :: "r"(saddr), "l"(gptr) : "memory")
#define CP_COMMIT() asm volatile("cp.async.commit_group;" ::: "memory")

#define LDSM_X4(r0, r1, r2, r3, a) \
    asm volatile("ldmatrix.sync.aligned.m8n8.x4.shared.b16 {%0,%1,%2,%3}, [%4];" \
        : "=r"(r0), "=r"(r1), "=r"(r2), "=r"(r3) : "r"(a))

#define HMMA(acc, a0, a1, a2, a3, b0, b1) \
    asm volatile( \
        "mma.sync.aligned.m16n8k16.row.col.f32.bf16.bf16.f32 " \
        "{%0,%1,%2,%3}, {%4,%5,%6,%7}, {%8,%9}, {%0,%1,%2,%3};\n" \
        : "+f"((acc)[0]), "+f"((acc)[1]), "+f"((acc)[2]), "+f"((acc)[3]) \
        : "r"(a0), "r"(a1), "r"(a2), "r"(a3), "r"(b0), "r"(b1))

// ---------------- weight fp32 -> bf16 ----------------
__global__ void convw_kernel(const float* __restrict__ wkvq, const float* __restrict__ wproj,
                             const float* __restrict__ wfc1, const float* __restrict__ wfc2) {
    int i = blockIdx.x * 256 + threadIdx.x;
    if (i < 3*CDIM*CDIM) g_wkvq[i]  = __float2bfloat16(wkvq[i]);
    if (i < CDIM*CDIM)   g_wproj[i] = __float2bfloat16(wproj[i]);
    if (i < HID*CDIM) {
        g_wfc1[i] = __float2bfloat16(wfc1[i]);
        g_wfc2[i] = __float2bfloat16(wfc2[i]);
    }
}

// ---------------- LN1: warp per row ----------------
__device__ __forceinline__ void warpLN8(float* v, float& mu, float& rstd) {
    float s = 0.f, s2 = 0.f;
    #pragma unroll
    for (int j = 0; j < 8; j++) { s += v[j]; s2 += v[j] * v[j]; }
    #pragma unroll
    for (int o = 16; o; o >>= 1) {
        s  += __shfl_xor_sync(0xffffffffu, s,  o);
        s2 += __shfl_xor_sync(0xffffffffu, s2, o);
    }
    mu = s * (1.f / CDIM);
    rstd = rsqrtf(s2 * (1.f / CDIM) - mu * mu + EPSLN);
}

__global__ void ln1_kernel(const float* __restrict__ x, const float* __restrict__ w,
                           const float* __restrict__ b) {
    int r = blockIdx.x * 8 + (threadIdx.x >> 5);
    int lane = threadIdx.x & 31;
    const float4* px = (const float4*)(x + (size_t)r * CDIM);
    float4 a0 = px[lane * 2], a1 = px[lane * 2 + 1];
    float v[8] = {a0.x, a0.y, a0.z, a0.w, a1.x, a1.y, a1.z, a1.w};
    float mu, rstd;
    warpLN8(v, mu, rstd);
    float4 w0 = ((const float4*)w)[lane*2], w1 = ((const float4*)w)[lane*2+1];
    float4 b0 = ((const float4*)b)[lane*2], b1 = ((const float4*)b)[lane*2+1];
    float wv[8] = {w0.x,w0.y,w0.z,w0.w,w1.x,w1.y,w1.z,w1.w};
    float bv[8] = {b0.x,b0.y,b0.z,b0.w,b1.x,b1.y,b1.z,b1.w};
    uint32_t o[4];
    #pragma unroll
    for (int j = 0; j < 4; j++) {
        float y0 = (v[2*j]   - mu) * rstd * wv[2*j]   + bv[2*j];
        float y1 = (v[2*j+1] - mu) * rstd * wv[2*j+1] + bv[2*j+1];
        o[j] = pack_bf2(y0, y1);
    }
    int ww = r % WDIM; int r2 = r / WDIM;
    int hh = r2 % HDIM; int bb = r2 / HDIM;
    int bh = bb / TDIM, t = bb - bh * TDIM;
    int m = ((bh * HDIM + hh) * WDIM + ww) * TDIM + t;
    ((uint4*)(g_xn + (size_t)m * CDIM))[lane] = make_uint4(o[0], o[1], o[2], o[3]);
}

// ------- attention: TWO threads per (n, head), 16 d-channels each; T=3 -------
__device__ __forceinline__ void u4tof(uint4 u, float2* f) {
    f[0] = __bfloat1622float2(*(__nv_bfloat162*)&u.x);
    f[1] = __bfloat1622float2(*(__nv_bfloat162*)&u.y);
    f[2] = __bfloat1622float2(*(__nv_bfloat162*)&u.z);
    f[3] = __bfloat1622float2(*(__nv_bfloat162*)&u.w);
}

__global__ void attn_kernel() {
    int gid = blockIdx.x * 256 + threadIdx.x;   // NTOK*16 threads
    int n = gid >> 4, h = (gid >> 1) & 7, half = gid & 1;
    const uint4* base = (const uint4*)(g_kvq + (size_t)n * 2304 + h * 32 + half * 16);
    float dot[3][3];
    #pragma unroll
    for (int a = 0; a < 3; a++)
        #pragma unroll
        for (int s = 0; s < 3; s++) dot[a][s] = 0.f;
    #pragma unroll
    for (int d8 = 0; d8 < 2; d8++) {
        float2 qv[3][4], kv[3][4];
        #pragma unroll
        for (int t = 0; t < 3; t++) {
            u4tof(base[(t*768 + 512) / 8 + d8], qv[t]);
            u4tof(base[(t*768 +   0) / 8 + d8], kv[t]);
        }
        #pragma unroll
        for (int a = 0; a < 3; a++)
            #pragma unroll
            for (int s = 0; s < 3; s++)
                #pragma unroll
                for (int j = 0; j < 4; j++)
                    dot[a][s] += qv[a][j].x * kv[s][j].x + qv[a][j].y * kv[s][j].y;
    }
    // merge the two halves (partner lane = lane ^ 1)
    #pragma unroll
    for (int a = 0; a < 3; a++)
        #pragma unroll
        for (int s = 0; s < 3; s++)
            dot[a][s] += __shfl_xor_sync(0xffffffffu, dot[a][s], 1);
    float wgt[3][3];
    #pragma unroll
    for (int a = 0; a < 3; a++) {
        float l0 = dot[a][0] * 0.17677669529663687f;
        float l1 = dot[a][1] * 0.17677669529663687f;
        float l2 = dot[a][2] * 0.17677669529663687f;
        float mx = fmaxf(l0, fmaxf(l1, l2));
        float e0 = __expf(l0 - mx), e1 = __expf(l1 - mx), e2 = __expf(l2 - mx);
        float inv = 1.f / (e0 + e1 + e2);
        wgt[a][0] = e0 * inv; wgt[a][1] = e1 * inv; wgt[a][2] = e2 * inv;
    }
    #pragma unroll
    for (int d8 = 0; d8 < 2; d8++) {
        float2 vv[3][4];
        #pragma unroll
        for (int t = 0; t < 3; t++) u4tof(base[(t*768 + 256) / 8 + d8], vv[t]);
        #pragma unroll
        for (int a = 0; a < 3; a++) {
            uint32_t o[4];
            #pragma unroll
            for (int j = 0; j < 4; j++) {
                float ox = wgt[a][0]*vv[0][j].x + wgt[a][1]*vv[1][j].x + wgt[a][2]*vv[2][j].x;
                float oy = wgt[a][0]*vv[0][j].y + wgt[a][1]*vv[1][j].y + wgt[a][2]*vv[2][j].y;
                o[j] = pack_bf2(ox, oy);
            }
            *(uint4*)(g_attn + (size_t)(n*3 + a) * CDIM + h*32 + half*16 + d8*8) =
                make_uint4(o[0], o[1], o[2], o[3]);
        }
    }
}

// ============== main GEMM: 128x128 tile, 4-stage ring, 1 sync/tile =============
#define BM 128
#define BN 128
#define BKK 32
#define LDSS 40                 /* 80B rows: conflict-free ldmatrix */
#define S4 4
#define STAGE_BYTES (BM * LDSS * 2)                 /* 10240, A or B */
#define GEMM_SMEM (S4 * 2 * STAGE_BYTES)            /* 81920 */

// EPI: 0 = kvq (bias -> bf16 g_kvq)   2 = fc1 (bias + gelu -> bf16 g_h)
//      3 = fc2 (bias + po + x residual -> fp32 out)
template<int EPI, int NDIM, int KDIM>
__global__ void __launch_bounds__(256, 2) gemm_kernel(const float* __restrict__ bias,
                                                      const float* __restrict__ xres,
                                                      float* __restrict__ gout) {
    constexpr int NKT = KDIM / BKK;
    const bf16 *A, *W;
    if constexpr (EPI == 0)      { A = g_xn;   W = g_wkvq;  }
    else if constexpr (EPI == 2) { A = g_xtn;  W = g_wfc1;  }
    else                         { A = g_h;    W = g_wfc2;  }

    extern __shared__ char dsm[];
    const uint32_t sA0 = s2u(dsm);
    const uint32_t sB0 = sA0 + S4 * STAGE_BYTES;

    const int bn = blockIdx.x, bm = blockIdx.y;
    const int tid = threadIdx.x;
    const int warp = tid >> 5, lane = tid & 31;
    const int wm = warp & 3, wn = warp >> 2;      // 4x2 warp grid, warp tile 32x64
    const int gro = lane >> 2, thr = lane & 3;
    const size_t aBase = (size_t)bm * BM * KDIM;
    const size_t bBase = (size_t)bn * BN * KDIM;

    const int aRow = wm * 32 + (lane & 7) + ((lane >> 3) & 1) * 8;
    const int aCol = (lane >> 4) * 8;
    const int bRow = wn * 64 + (lane & 7) + (lane >> 4) * 8;
    const int bCol = ((lane >> 3) & 1) * 8;

    const int lrow = tid >> 2, lch = tid & 3;
    auto loadTile = [&](int st, int kt) {
        int k0 = kt * BKK;
        uint32_t dA = sA0 + st * STAGE_BYTES + (uint32_t)((lrow * LDSS + lch * 8) * 2);
        uint32_t dB = sB0 + st * STAGE_BYTES + (uint32_t)((lrow * LDSS + lch * 8) * 2);
        const bf16* ga = A + aBase + (size_t)lrow * KDIM + k0 + lch * 8;
        const bf16* gb = W + bBase + (size_t)lrow * KDIM + k0 + lch * 8;
        CP_ASYNC16(dA, ga);
        CP_ASYNC16(dA + (uint32_t)(64 * LDSS * 2), ga + (size_t)64 * KDIM);
        CP_ASYNC16(dB, gb);
        CP_ASYNC16(dB + (uint32_t)(64 * LDSS * 2), gb + (size_t)64 * KDIM);
        CP_COMMIT();
    };

    float acc[2][8][4];
    #pragma unroll
    for (int i = 0; i < 2; i++)
        #pragma unroll
        for (int j = 0; j < 8; j++)
            #pragma unroll
            for (int l = 0; l < 4; l++) acc[i][j][l] = 0.f;

    #pragma unroll
    for (int s = 0; s < S4 - 1; s++) loadTile(s, s);

    for (int kt = 0; kt < NKT; kt++) {
        if (kt < NKT - 2)       asm volatile("cp.async.wait_group 2;" ::: "memory");
        else if (kt == NKT - 2) asm volatile("cp.async.wait_group 1;" ::: "memory");
        else                    asm volatile("cp.async.wait_group 0;" ::: "memory");
        __syncthreads();
        if (kt + S4 - 1 < NKT) loadTile((kt + S4 - 1) & (S4 - 1), kt + S4 - 1);
        const int st = kt & (S4 - 1);
        #pragma unroll
        for (int ks = 0; ks < 2; ks++) {
            uint32_t af[2][4];
            #pragma unroll
            for (int mi = 0; mi < 2; mi++) {
                uint32_t addr = sA0 + st * STAGE_BYTES +
                    (uint32_t)(((aRow + mi * 16) * LDSS + ks * 16 + aCol) * 2);
                LDSM_X4(af[mi][0], af[mi][1], af[mi][2], af[mi][3], addr);
            }
            uint32_t bfr[8][2];
            #pragma unroll
            for (int pr = 0; pr < 4; pr++) {
                uint32_t addr = sB0 + st * STAGE_BYTES +
                    (uint32_t)(((bRow + pr * 16) * LDSS + ks * 16 + bCol) * 2);
                LDSM_X4(bfr[pr*2][0], bfr[pr*2][1], bfr[pr*2+1][0], bfr[pr*2+1][1], addr);
            }
            #pragma unroll
            for (int ni = 0; ni < 8; ni++)
                #pragma unroll
                for (int mi = 0; mi < 2; mi++)
                    HMMA(acc[mi][ni], af[mi][0], af[mi][1], af[mi][2], af[mi][3],
                         bfr[ni][0], bfr[ni][1]);
        }
    }

    // ---- epilogue ----
    const int cb = bn * BN + wn * 64 + thr * 2;
    #pragma unroll
    for (int mi = 0; mi < 2; mi++) {
        #pragma unroll
        for (int rr = 0; rr < 2; rr++) {
            int m = bm * BM + wm * 32 + mi * 16 + rr * 8 + gro;
            size_t xidx = 0;
            if constexpr (EPI == 3) {
                int t = m % 3;
                int n = m / 3;
                int ww = n % WDIM;
                int r2 = n / WDIM;
                int hh = r2 % HDIM;
                int bhat = r2 / HDIM;
                int b = bhat * TDIM + t;
                xidx = ((size_t)((b * HDIM + hh) * WDIM + ww)) * CDIM;
            }
            #pragma unroll
            for (int ni = 0; ni < 8; ni++) {
                int c = cb + ni * 8;
                float v0 = acc[mi][ni][rr * 2 + 0] + bias[c];
                float v1 = acc[mi][ni][rr * 2 + 1] + bias[c + 1];
                if constexpr (EPI == 0) {
                    *(uint32_t*)&g_kvq[(size_t)m * NDIM + c] = pack_bf2(v0, v1);
                } else if constexpr (EPI == 2) {
                    v0 = 0.5f * v0 * (1.f + erff(v0 * 0.7071067811865475f));
                    v1 = 0.5f * v1 * (1.f + erff(v1 * 0.7071067811865475f));
                    *(uint32_t*)&g_h[(size_t)m * NDIM + c] = pack_bf2(v0, v1);
                } else {
                    float2 pp = __bfloat1622float2(*(const __nv_bfloat162*)&g_po[(size_t)m * CDIM + c]);
                    float2 xx = *(const float2*)&xres[xidx + c];
                    *(float2*)&gout[xidx + c] = make_float2(v0 + pp.x + xx.x, v1 + pp.y + xx.y);
                }
            }
        }
    }
}

// ====== fused proj + residual + LN2: 64-row x full-256-col tile, 3-stage ring ======
#define PBM 64
#define PS 3
#define PA_BYTES (PBM * LDSS * 2)     /* 5120 */
#define PB_BYTES (CDIM * LDSS * 2)    /* 20480 */
#define PSTAGE (PA_BYTES + PB_BYTES)  /* 25600 */
#define PROJ_SMEM (PS * PSTAGE)       /* 76800 */

__global__ void __launch_bounds__(256, 2) projln_kernel(const float* __restrict__ bias,
                                                        const float* __restrict__ x,
                                                        const float* __restrict__ w2,
                                                        const float* __restrict__ b2) {
    constexpr int NKT = CDIM / BKK;   // 8
    extern __shared__ char dsm[];
    __shared__ float2 red[PBM][2];

    const uint32_t p0 = s2u(dsm);
    const int bm = blockIdx.x;
    const int tid = threadIdx.x;
    const int warp = tid >> 5, lane = tid & 31;
    const int wm = warp & 3, wn = warp >> 2;      // 4 (m) x 2 (n); warp tile 16x128
    const int gro = lane >> 2, thr = lane & 3;
    const size_t aBase = (size_t)bm * PBM * CDIM;

    const int aRow = wm * 16 + (lane & 7) + ((lane >> 3) & 1) * 8;
    const int aCol = (lane >> 4) * 8;
    const int bRow = wn * 128 + (lane & 7) + (lane >> 4) * 8;
    const int bCol = ((lane >> 3) & 1) * 8;

    auto loadTile = [&](int st, int kt) {
        int k0 = kt * BKK;
        uint32_t base = p0 + st * PSTAGE;
        {
            int row = tid >> 2, ch = tid & 3;
            CP_ASYNC16(base + (uint32_t)((row * LDSS + ch * 8) * 2),
                       g_attn + aBase + (size_t)row * CDIM + k0 + ch * 8);
        }
        {
            uint32_t bB = base + PA_BYTES;
            #pragma unroll
            for (int i = 0; i < 4; i++) {
                int idx = tid + i * 256;
                int row = idx >> 2, ch = idx & 3;
                CP_ASYNC16(bB + (uint32_t)((row * LDSS + ch * 8) * 2),
                           g_wproj + (size_t)row * CDIM + k0 + ch * 8);
            }
        }
        CP_COMMIT();
    };

    float acc[16][4];
    #pragma unroll
    for (int j = 0; j < 16; j++)
        #pragma unroll
        for (int l = 0; l < 4; l++) acc[j][l] = 0.f;

    loadTile(0, 0);
    loadTile(1, 1);
    for (int kt = 0; kt < NKT; kt++) {
        if (kt < NKT - 1) asm volatile("cp.async.wait_group 1;" ::: "memory");
        else              asm volatile("cp.async.wait_group 0;" ::: "memory");
        __syncthreads();
        if (kt + 2 < NKT) loadTile((kt + 2) % PS, kt + 2);
        const int st = kt % PS;
        uint32_t base = p0 + st * PSTAGE;
        #pragma unroll
        for (int ks = 0; ks < 2; ks++) {
            uint32_t af[4];
            LDSM_X4(af[0], af[1], af[2], af[3],
                    base + (uint32_t)((aRow * LDSS + ks * 16 + aCol) * 2));
            uint32_t bfr[16][2];
            #pragma unroll
            for (int pr = 0; pr < 8; pr++) {
                uint32_t addr = base + PA_BYTES +
                    (uint32_t)(((bRow + pr * 16) * LDSS + ks * 16 + bCol) * 2);
                LDSM_X4(bfr[pr*2][0], bfr[pr*2][1], bfr[pr*2+1][0], bfr[pr*2+1][1], addr);
            }
            #pragma unroll
            for (int ni = 0; ni < 16; ni++)
                HMMA(acc[ni], af[0], af[1], af[2], af[3], bfr[ni][0], bfr[ni][1]);
        }
    }

    // ---- epilogue: bias, write po(bf16), +x -> LN over full row -> xtn ----
    size_t xidx[2];
    #pragma unroll
    for (int rr = 0; rr < 2; rr++) {
        int ml = wm * 16 + rr * 8 + gro;
        int m = bm * PBM + ml;
        int t = m % 3;
        int n = m / 3;
        int ww = n % WDIM;
        int r2 = n / WDIM;
        int hh = r2 % HDIM;
        int bhat = r2 / HDIM;
        xidx[rr] = ((size_t)(((bhat * TDIM + t) * HDIM + hh) * WDIM + ww)) * CDIM;

        float s = 0.f, s2 = 0.f;
        #pragma unroll
        for (int ni = 0; ni < 16; ni++) {
            int c = wn * 128 + ni * 8 + thr * 2;
            float2 bb = *(const float2*)&bias[c];
            float v0 = acc[ni][rr*2+0] + bb.x;
            float v1 = acc[ni][rr*2+1] + bb.y;
            *(uint32_t*)&g_po[(size_t)m * CDIM + c] = pack_bf2(v0, v1);
            float2 xx = *(const float2*)&x[xidx[rr] + c];
            v0 += xx.x; v1 += xx.y;
            acc[ni][rr*2+0] = v0; acc[ni][rr*2+1] = v1;
            s += v0 + v1; s2 += v0*v0 + v1*v1;
        }
        #pragma unroll
        for (int o = 1; o < 4; o <<= 1) {
            s  += __shfl_xor_sync(0xffffffffu, s,  o);
            s2 += __shfl_xor_sync(0xffffffffu, s2, o);
        }
        if (thr == 0) red[ml][wn] = make_float2(s, s2);
    }
    __syncthreads();
    #pragma unroll
    for (int rr = 0; rr < 2; rr++) {
        int ml = wm * 16 + rr * 8 + gro;
        int m = bm * PBM + ml;
        float2 rA = red[ml][0], rB = red[ml][1];
        float mu = (rA.x + rB.x) * (1.f / CDIM);
        float var = (rA.y + rB.y) * (1.f / CDIM) - mu * mu;
        float rstd = rsqrtf(var + EPSLN);
        #pragma unroll
        for (int ni = 0; ni < 16; ni++) {
            int c = wn * 128 + ni * 8 + thr * 2;
            float2 ww2 = *(const float2*)&w2[c];
            float2 bb2 = *(const float2*)&b2[c];
            float y0 = (acc[ni][rr*2+0] - mu) * rstd * ww2.x + bb2.x;
            float y1 = (acc[ni][rr*2+1] - mu) * rstd * ww2.y + bb2.y;
            *(uint32_t*)&g_xtn[(size_t)m * CDIM + c] = pack_bf2(y0, y1);
        }
    }
}

// ---------------- launch ----------------
extern "C" void kernel_launch(void* const* d_in, const int* in_sizes, int n_in,
                              void* d_out, int out_size) {
    const float* x      = (const float*)d_in[0];
    const float* n1w    = (const float*)d_in[1];
    const float* n1b    = (const float*)d_in[2];
    const float* kvq_w  = (const float*)d_in[3];
    const float* kvq_b  = (const float*)d_in[4];
    const float* proj_w = (const float*)d_in[5];
    const float* proj_b = (const float*)d_in[6];
    const float* n2w    = (const float*)d_in[7];
    const float* n2b    = (const float*)d_in[8];
    const float* fc1_w  = (const float*)d_in[9];
    const float* fc1_b  = (const float*)d_in[10];
    const float* fc2_w  = (const float*)d_in[11];
    const float* fc2_b  = (const float*)d_in[12];
    float* out = (float*)d_out;

    static bool attrs_set = false;
    if (!attrs_set) {
        cudaFuncSetAttribute(gemm_kernel<0, 768, 256>,  cudaFuncAttributeMaxDynamicSharedMemorySize, GEMM_SMEM);
        cudaFuncSetAttribute(gemm_kernel<2, 1024, 256>, cudaFuncAttributeMaxDynamicSharedMemorySize, GEMM_SMEM);
        cudaFuncSetAttribute(gemm_kernel<3, 256, 1024>, cudaFuncAttributeMaxDynamicSharedMemorySize, GEMM_SMEM);
        cudaFuncSetAttribute(projln_kernel,             cudaFuncAttributeMaxDynamicSharedMemorySize, PROJ_SMEM);
        attrs_set = true;
    }

    convw_kernel<<<1024, 256>>>(kvq_w, proj_w, fc1_w, fc2_w);
    ln1_kernel<<<MROWS / 8, 256>>>(x, n1w, n1b);
    gemm_kernel<0, 768, 256><<<dim3(6, MROWS / BM), 256, GEMM_SMEM>>>(kvq_b, nullptr, nullptr);
    attn_kernel<<<(NTOK * 16) / 256, 256>>>();
    projln_kernel<<<MROWS / PBM, 256, PROJ_SMEM>>>(proj_b, x, n2w, n2b);
    gemm_kernel<2, 1024, 256><<<dim3(8, MROWS / BM), 256, GEMM_SMEM>>>(fc1_b, nullptr, nullptr);
    gemm_kernel<3, 256, 1024><<<dim3(2, MROWS / BM), 256, GEMM_SMEM>>>(fc2_b, x, out);
}